// round 8
// baseline (speedup 1.0000x reference)
#include <cuda_runtime.h>

#define TOK_TOTAL 65536
#define TOK_HALF  32768
#define HD 1024
#define NLEV 4

// Scratch (static device globals; no runtime allocation allowed)
__device__ float g_H[(size_t)TOK_TOTAL * HD];    // 256MB hidden activations
__device__ float g_logits[TOK_TOTAL * NLEV];     // 1MB
__device__ int   g_idx[NLEV * TOK_TOTAL];        // 1MB bucketed token ids
__device__ int   g_count[NLEV];

struct CompParams {
    const float* keys;
    const float* values;
    const float* w1[NLEV];
    const float* b1[NLEV];
    const float* w2[NLEV];
    const float* b2[NLEV];
    float* out;
};

// ---------------------------------------------------------------------------
// Shared SGEMM mainloop: BM=BN=128, BK=8, 256 threads, 8x8 microtile.
// a_ptr: per-thread pointer to A[row, kA] (row fixed, advanced by k0).
// b_ptr: B + n0 (element (k, n_local) at b_ptr[k*ldb + n_local]).
// ---------------------------------------------------------------------------
__device__ __forceinline__ void gemm_mainloop(
    const float* a_ptr, const float* b_ptr, int ldb, int K,
    float (&c)[8][8], float (*As)[128], float (*Bs)[128])
{
    const int tid  = threadIdx.x;
    const int rowA = tid & 127;
    const int kA   = (tid >> 7) << 2;     (void)kA;
    const int kB   = tid >> 5;
    const int nB   = (tid & 31) << 2;
    const int tx   = tid & 15;
    const int ty   = tid >> 4;

    float4 av = *(const float4*)(a_ptr);
    float4 bv = *(const float4*)(b_ptr + (size_t)kB * ldb + nB);

    for (int k0 = 0; k0 < K; k0 += 8) {
        __syncthreads();
        As[((tid >> 7) << 2) + 0][rowA] = av.x;
        As[((tid >> 7) << 2) + 1][rowA] = av.y;
        As[((tid >> 7) << 2) + 2][rowA] = av.z;
        As[((tid >> 7) << 2) + 3][rowA] = av.w;
        *(float4*)&Bs[kB][nB] = bv;
        __syncthreads();
        if (k0 + 8 < K) {
            av = *(const float4*)(a_ptr + k0 + 8);
            bv = *(const float4*)(b_ptr + (size_t)(k0 + 8 + kB) * ldb + nB);
        }
#pragma unroll
        for (int kk = 0; kk < 8; kk++) {
            float4 a0 = *(float4*)&As[kk][ty * 4];
            float4 a1 = *(float4*)&As[kk][64 + ty * 4];
            float4 b0 = *(float4*)&Bs[kk][tx * 4];
            float4 b1 = *(float4*)&Bs[kk][64 + tx * 4];
            float a[8] = {a0.x, a0.y, a0.z, a0.w, a1.x, a1.y, a1.z, a1.w};
            float b[8] = {b0.x, b0.y, b0.z, b0.w, b1.x, b1.y, b1.z, b1.w};
#pragma unroll
            for (int i = 0; i < 8; i++)
#pragma unroll
                for (int j = 0; j < 8; j++)
                    c[i][j] = fmaf(a[i], b[j], c[i][j]);
        }
    }
}

__device__ __forceinline__ int rmap(int ty, int i) {
    return (i < 4) ? (ty * 4 + i) : (64 + ty * 4 + (i - 4));
}
__device__ __forceinline__ int cmap(int tx, int j) {
    return (j < 4) ? (tx * 4 + j) : (64 + tx * 4 + (j - 4));
}

// ---------------------------------------------------------------------------
// Zero scratch (logits + bucket counts)
// ---------------------------------------------------------------------------
__global__ void zero_kernel() {
    int i = blockIdx.x * 256 + threadIdx.x;
    if (i < TOK_TOTAL * NLEV) g_logits[i] = 0.f;
    if (i < NLEV) g_count[i] = 0;
}

// ---------------------------------------------------------------------------
// Predictor: C = X @ W1cat (N=1024 = 4 levels x 256), epilogue reduces
// relu(c + b1) * w2 over columns of each level-segment into g_logits.
// grid (8, 256, 2): z=0 keys, z=1 values.
// ---------------------------------------------------------------------------
__global__ __launch_bounds__(256, 2) void predictor_kernel(
    const float* __restrict__ keys, const float* __restrict__ values,
    const float* __restrict__ Pw1, const float* __restrict__ Pb1,
    const float* __restrict__ Pw2)
{
    __shared__ float As[8][128], Bs[8][128];
    const int tid = threadIdx.x;
    const int bx = blockIdx.x, by = blockIdx.y, bz = blockIdx.z;
    const float* X = bz ? values : keys;
    const int tokbase = bz * TOK_HALF + by * 128;

    const int n0  = bx * 128;
    const int lev = n0 >> 8;           // 128-col tile lies within one level
    const int jc  = n0 & 255;
    const float* Bp = Pw1 + (size_t)lev * HD * 256 + jc;   // [k][j], ldb=256

    const int rowA = tid & 127, kA = (tid >> 7) << 2;
    const float* a_ptr = X + (size_t)(by * 128 + rowA) * HD + kA;

    float c[8][8];
#pragma unroll
    for (int i = 0; i < 8; i++)
#pragma unroll
        for (int j = 0; j < 8; j++) c[i][j] = 0.f;

    gemm_mainloop(a_ptr, Bp, 256, HD, c, As, Bs);

    const int tx = tid & 15, ty = tid >> 4;
    float w2v[8], b1v[8];
#pragma unroll
    for (int j = 0; j < 8; j++) {
        int n = n0 + cmap(tx, j);      // global col == flat index into Pb1/Pw2
        w2v[j] = Pw2[n];
        b1v[j] = Pb1[n];
    }
    float part[8];
#pragma unroll
    for (int i = 0; i < 8; i++) {
        float s = 0.f;
#pragma unroll
        for (int j = 0; j < 8; j++)
            s += fmaxf(c[i][j] + b1v[j], 0.f) * w2v[j];
        part[i] = s;
    }
    for (int off = 8; off >= 1; off >>= 1)
#pragma unroll
        for (int i = 0; i < 8; i++)
            part[i] += __shfl_xor_sync(0xffffffffu, part[i], off, 16);
    if (tx == 0) {
#pragma unroll
        for (int i = 0; i < 8; i++) {
            int r = rmap(ty, i);
            atomicAdd(&g_logits[(size_t)(tokbase + r) * NLEV + lev], part[i]);
        }
    }
}

// ---------------------------------------------------------------------------
// Argmax (sigmoid is monotone -> argmax of raw logits) + bucket compaction.
// ---------------------------------------------------------------------------
__global__ void argmax_kernel(const float* __restrict__ Pb2) {
    int t = blockIdx.x * 256 + threadIdx.x;
    if (t >= TOK_TOTAL) return;
    float best = g_logits[t * NLEV] + Pb2[0];
    int bl = 0;
#pragma unroll
    for (int l = 1; l < NLEV; l++) {
        float v = g_logits[t * NLEV + l] + Pb2[l];
        if (v > best) { best = v; bl = l; }   // strict > = first-max tiebreak
    }
    int p = atomicAdd(&g_count[bl], 1);
    g_idx[bl * TOK_TOTAL + p] = t;
}

// ---------------------------------------------------------------------------
// Stage A: H = relu(Xg @ w1_l + b1_l). grid (8, 512, 4), early-exit on
// d/count. A-rows gathered by bucket; H stored by token id (ld=1024).
// ---------------------------------------------------------------------------
__global__ __launch_bounds__(256, 2) void stageA_kernel(CompParams P) {
    const int lev = blockIdx.z;
    const int d = HD >> lev;
    const int n0 = blockIdx.x * 128;
    if (n0 >= d) return;
    const int cnt = g_count[lev];
    const int m0 = blockIdx.y * 128;
    if (m0 >= cnt) return;

    __shared__ float As[8][128], Bs[8][128];
    const int tid = threadIdx.x;
    const int rowA = tid & 127, kA = (tid >> 7) << 2;
    int rload = m0 + rowA; if (rload > cnt - 1) rload = cnt - 1;
    const int tl = g_idx[lev * TOK_TOTAL + rload];
    const float* arow = (tl < TOK_HALF)
        ? (P.keys + (size_t)tl * HD)
        : (P.values + (size_t)(tl - TOK_HALF) * HD);

    float c[8][8];
#pragma unroll
    for (int i = 0; i < 8; i++)
#pragma unroll
        for (int j = 0; j < 8; j++) c[i][j] = 0.f;

    gemm_mainloop(arow + kA, P.w1[lev] + n0, d, HD, c, As, Bs);

    const int tx = tid & 15, ty = tid >> 4;
    const float* b1 = P.b1[lev] + n0;
    float b1v[8];
#pragma unroll
    for (int j = 0; j < 8; j++) b1v[j] = b1[cmap(tx, j)];

#pragma unroll
    for (int i = 0; i < 8; i++) {
        int r = m0 + rmap(ty, i);
        if (r < cnt) {
            int t = g_idx[lev * TOK_TOTAL + r];
            float* dst = g_H + (size_t)t * HD + n0;
            float4 v0, v1;
            v0.x = fmaxf(c[i][0] + b1v[0], 0.f);
            v0.y = fmaxf(c[i][1] + b1v[1], 0.f);
            v0.z = fmaxf(c[i][2] + b1v[2], 0.f);
            v0.w = fmaxf(c[i][3] + b1v[3], 0.f);
            v1.x = fmaxf(c[i][4] + b1v[4], 0.f);
            v1.y = fmaxf(c[i][5] + b1v[5], 0.f);
            v1.z = fmaxf(c[i][6] + b1v[6], 0.f);
            v1.w = fmaxf(c[i][7] + b1v[7], 0.f);
            *(float4*)(dst + tx * 4)      = v0;
            *(float4*)(dst + 64 + tx * 4) = v1;
        }
    }
}

// ---------------------------------------------------------------------------
// Stage B: out = H @ w2_l + b2_l, scattered to out rows by token id.
// out layout: [keys_out | values_out] -> token t maps to out + t*1024.
// ---------------------------------------------------------------------------
__global__ __launch_bounds__(256, 2) void stageB_kernel(CompParams P) {
    const int lev = blockIdx.z;
    const int d = HD >> lev;               // K dimension
    const int n0 = blockIdx.x * 128;       // N = 1024
    const int cnt = g_count[lev];
    const int m0 = blockIdx.y * 128;
    if (m0 >= cnt) return;

    __shared__ float As[8][128], Bs[8][128];
    const int tid = threadIdx.x;
    const int rowA = tid & 127, kA = (tid >> 7) << 2;
    int rload = m0 + rowA; if (rload > cnt - 1) rload = cnt - 1;
    const int tl = g_idx[lev * TOK_TOTAL + rload];

    float c[8][8];
#pragma unroll
    for (int i = 0; i < 8; i++)
#pragma unroll
        for (int j = 0; j < 8; j++) c[i][j] = 0.f;

    gemm_mainloop(g_H + (size_t)tl * HD + kA, P.w2[lev] + n0, HD, d, c, As, Bs);

    const int tx = tid & 15, ty = tid >> 4;
    const float* b2 = P.b2[lev] + n0;
    float b2v[8];
#pragma unroll
    for (int j = 0; j < 8; j++) b2v[j] = b2[cmap(tx, j)];

#pragma unroll
    for (int i = 0; i < 8; i++) {
        int r = m0 + rmap(ty, i);
        if (r < cnt) {
            int t = g_idx[lev * TOK_TOTAL + r];
            float* dst = P.out + (size_t)t * HD + n0;
            float4 v0, v1;
            v0.x = c[i][0] + b2v[0];
            v0.y = c[i][1] + b2v[1];
            v0.z = c[i][2] + b2v[2];
            v0.w = c[i][3] + b2v[3];
            v1.x = c[i][4] + b2v[4];
            v1.y = c[i][5] + b2v[5];
            v1.z = c[i][6] + b2v[6];
            v1.w = c[i][7] + b2v[7];
            *(float4*)(dst + tx * 4)      = v0;
            *(float4*)(dst + 64 + tx * 4) = v1;
        }
    }
}

// ---------------------------------------------------------------------------
extern "C" void kernel_launch(void* const* d_in, const int* in_sizes, int n_in,
                              void* d_out, int out_size) {
    const float* keys   = (const float*)d_in[0];
    const float* values = (const float*)d_in[1];
    const float* Pw1    = (const float*)d_in[2];
    const float* Pb1    = (const float*)d_in[3];
    const float* Pw2    = (const float*)d_in[4];
    const float* Pb2    = (const float*)d_in[5];

    CompParams P;
    P.keys = keys; P.values = values;
    for (int l = 0; l < 4; l++) {
        P.w1[l] = (const float*)d_in[6 + l * 4 + 0];
        P.b1[l] = (const float*)d_in[6 + l * 4 + 1];
        P.w2[l] = (const float*)d_in[6 + l * 4 + 2];
        P.b2[l] = (const float*)d_in[6 + l * 4 + 3];
    }
    P.out = (float*)d_out;

    zero_kernel<<<(TOK_TOTAL * NLEV + 255) / 256, 256>>>();

    dim3 pgrid(8, 256, 2);                 // N-tiles, M-tiles (32768/128), keys|values
    predictor_kernel<<<pgrid, 256>>>(keys, values, Pw1, Pb1, Pw2);

    argmax_kernel<<<TOK_TOTAL / 256, 256>>>(Pb2);

    dim3 cgrid(8, 512, 4);                 // N-tiles, M-tiles (65536/128), levels
    stageA_kernel<<<cgrid, 256>>>(P);
    stageB_kernel<<<cgrid, 256>>>(P);
}

// round 10
// speedup vs baseline: 1.1604x; 1.1604x over previous
#include <cuda_runtime.h>
#include <cuda_bf16.h>
#include <cstdint>

#define TOK_TOTAL 65536
#define TOK_HALF  32768
#define HD 1024
#define NLEV 4
#define MAX_AMB 8192
#define AMB_THRESH 2e-3f

// ---------------------------------------------------------------------------
// Scratch (static device globals; no runtime allocation allowed)
// ---------------------------------------------------------------------------
__device__ float g_logits[TOK_TOTAL * NLEV];
__device__ int   g_idx[NLEV * TOK_TOTAL];
__device__ int   g_count[NLEV];
__device__ int   g_amb[MAX_AMB];
__device__ int   g_amb_count;

// Hidden activations, pre-split to bf16 hi/lo
__device__ __nv_bfloat16 g_Hhi[(size_t)TOK_TOTAL * HD];
__device__ __nv_bfloat16 g_Hlo[(size_t)TOK_TOTAL * HD];

// Transposed + bf16-split weights (K-major: row n, contiguous k)
#define WT_TOTAL 1966080   // sum over levels of d*1024
__device__ __nv_bfloat16 g_w1t_hi[WT_TOTAL], g_w1t_lo[WT_TOTAL];
__device__ __nv_bfloat16 g_w2t_hi[WT_TOTAL], g_w2t_lo[WT_TOTAL];
// Predictor W1 transposed: [n=l*256+j][k], 1024x1024
__device__ __nv_bfloat16 g_pw1t_hi[HD * HD], g_pw1t_lo[HD * HD];

__device__ __forceinline__ size_t WOFF(int l) {
    return (l == 0) ? 0 : (l == 1) ? 1048576 : (l == 2) ? 1572864 : 1835008;
}

struct CompParams {
    const float* keys;
    const float* values;
    const float* w1[NLEV];
    const float* b1[NLEV];
    const float* w2[NLEV];
    const float* b2[NLEV];
    float* out;
};

// ---------------------------------------------------------------------------
// Low-level helpers
// ---------------------------------------------------------------------------
__device__ __forceinline__ uint32_t smem_to_u32(const void* p) {
    uint32_t a;
    asm("{ .reg .u64 t; cvta.to.shared.u64 t, %1; cvt.u32.u64 %0, t; }"
        : "=r"(a) : "l"(p));
    return a;
}
#define STS128(a, r0, r1, r2, r3) \
    asm volatile("st.shared.v4.b32 [%0], {%1, %2, %3, %4};" \
        :: "r"(a), "r"(r0), "r"(r1), "r"(r2), "r"(r3) : "memory")
#define SWZ(off) ((off) ^ (((off) >> 3) & 0x70))

__device__ __forceinline__ void ldsm_x4(uint32_t (&r)[4], uint32_t addr) {
    asm volatile("ldmatrix.sync.aligned.m8n8.x4.shared.b16 {%0,%1,%2,%3}, [%4];"
        : "=r"(r[0]), "=r"(r[1]), "=r"(r[2]), "=r"(r[3]) : "r"(addr));
}
__device__ __forceinline__ void mma_bf16(float (&d)[4], const uint32_t (&a)[4],
                                         uint32_t b0, uint32_t b1) {
    asm volatile(
        "mma.sync.aligned.m16n8k16.row.col.f32.bf16.bf16.f32 "
        "{%0,%1,%2,%3}, {%4,%5,%6,%7}, {%8,%9}, {%0,%1,%2,%3};"
        : "+f"(d[0]), "+f"(d[1]), "+f"(d[2]), "+f"(d[3])
        : "r"(a[0]), "r"(a[1]), "r"(a[2]), "r"(a[3]), "r"(b0), "r"(b1));
}

// bf16 hi/lo split, packed as bf16x2 words (low half = lower index)
__device__ __forceinline__ uint32_t pack_split(float a, float b, uint32_t& lo_out) {
    __nv_bfloat16 ha = __float2bfloat16(a), hb = __float2bfloat16(b);
    float ra = a - __bfloat162float(ha);
    float rb = b - __bfloat162float(hb);
    __nv_bfloat16 la = __float2bfloat16(ra), lb = __float2bfloat16(rb);
    lo_out = ((uint32_t)__bfloat16_as_ushort(lb) << 16) | (uint32_t)__bfloat16_as_ushort(la);
    return ((uint32_t)__bfloat16_as_ushort(hb) << 16) | (uint32_t)__bfloat16_as_ushort(ha);
}

// ---------------------------------------------------------------------------
// Dynamic smem layout (relative to 1024-aligned base)
// Buffers: 4 x [128 rows x 64 bf16] swizzled (16KB each).
// Accum staging (fp32 128x132) overlays the same region.
// ---------------------------------------------------------------------------
#define SM_AHI   0
#define SM_ALO   16384
#define SM_BHI   32768
#define SM_BLO   49152
#define SM_REGION 69632          // >= max(65536, 128*132*4=67584)
#define ACC_LD   132
#define SMEM_BYTES (SM_REGION + 1024)   // + alignment slack

// ---------------------------------------------------------------------------
// MMA microkernel: one K=64 chunk, 3-product bf16 split.
// Block tile 128x128, 8 warps: wy=wid>>1 (m 32), wx=wid&1 (n 64).
// Accum acc[mt(2)][nt(8)][4].
// ---------------------------------------------------------------------------
__device__ __forceinline__ void mma_chunk(
    uint32_t sAhi, uint32_t sAlo, uint32_t sBhi, uint32_t sBlo,
    int m_base, int n_base, int lane, float (*acc)[8][4])
{
#pragma unroll
    for (int ks = 0; ks < 4; ks++) {
        const int k0 = ks * 16;
        const uint32_t arow = (uint32_t)(m_base + (lane & 15));
        const uint32_t acol = (uint32_t)(k0 + ((lane >> 4) << 3));
        uint32_t ahi[2][4], alo[2][4];
#pragma unroll
        for (int mt = 0; mt < 2; mt++) {
            uint32_t off = SWZ((arow + mt * 16) * 128 + acol * 2);
            ldsm_x4(ahi[mt], sAhi + off);
            ldsm_x4(alo[mt], sAlo + off);
        }
        const uint32_t brow = (uint32_t)((lane & 7) + ((lane >> 4) << 3));
        const uint32_t bcol = (uint32_t)(k0 + (((lane >> 3) & 1) << 3));
        uint32_t bhi[8][2], blo[8][2];
#pragma unroll
        for (int ng = 0; ng < 4; ng++) {
            uint32_t off = SWZ((uint32_t)(n_base + ng * 16 + brow) * 128 + bcol * 2);
            uint32_t t[4];
            ldsm_x4(t, sBhi + off);
            bhi[ng * 2][0] = t[0]; bhi[ng * 2][1] = t[1];
            bhi[ng * 2 + 1][0] = t[2]; bhi[ng * 2 + 1][1] = t[3];
            ldsm_x4(t, sBlo + off);
            blo[ng * 2][0] = t[0]; blo[ng * 2][1] = t[1];
            blo[ng * 2 + 1][0] = t[2]; blo[ng * 2 + 1][1] = t[3];
        }
#pragma unroll
        for (int mt = 0; mt < 2; mt++)
#pragma unroll
            for (int nt = 0; nt < 8; nt++) {
                mma_bf16(acc[mt][nt], ahi[mt], bhi[nt][0], bhi[nt][1]);
                mma_bf16(acc[mt][nt], ahi[mt], blo[nt][0], blo[nt][1]);
                mma_bf16(acc[mt][nt], alo[mt], bhi[nt][0], bhi[nt][1]);
            }
    }
}

// Store accum tile to padded fp32 smem (for coalesced epilogues)
__device__ __forceinline__ void stage_acc(float* acc_s, int m_base, int n_base,
                                          int lane, float (*acc)[8][4]) {
#pragma unroll
    for (int mt = 0; mt < 2; mt++)
#pragma unroll
        for (int nt = 0; nt < 8; nt++) {
            int row = m_base + mt * 16 + (lane >> 2);
            int col = n_base + nt * 8 + ((lane & 3) << 1);
            float* p = acc_s + (size_t)row * ACC_LD + col;
            p[0] = acc[mt][nt][0];
            p[1] = acc[mt][nt][1];
            p[8 * ACC_LD] = acc[mt][nt][2];
            p[8 * ACC_LD + 1] = acc[mt][nt][3];
        }
}

// ---------------------------------------------------------------------------
__global__ void zero_kernel() {
    int i = blockIdx.x * 256 + threadIdx.x;
    if (i < TOK_TOTAL * NLEV) g_logits[i] = 0.f;
    if (i < NLEV) g_count[i] = 0;
    if (i == 0) g_amb_count = 0;
}

// ---------------------------------------------------------------------------
// Weight prep: transpose + bf16 hi/lo split for compress weights and Pw1.
// ---------------------------------------------------------------------------
__global__ void prep_kernel(CompParams P, const float* __restrict__ Pw1) {
    int l = blockIdx.y;
    int d = HD >> l;
    size_t base = WOFF(l);
    int total = d * HD;
    for (int i = blockIdx.x * 256 + threadIdx.x; i < total; i += gridDim.x * 256) {
        int n = i / HD, k = i - n * HD;
        float v = P.w1[l][(size_t)k * d + n];
        __nv_bfloat16 h = __float2bfloat16(v);
        g_w1t_hi[base + i] = h;
        g_w1t_lo[base + i] = __float2bfloat16(v - __bfloat162float(h));
        int n2 = i / d, k2 = i - n2 * d;
        float v2 = P.w2[l][(size_t)k2 * HD + n2];
        __nv_bfloat16 h2 = __float2bfloat16(v2);
        g_w2t_hi[base + i] = h2;
        g_w2t_lo[base + i] = __float2bfloat16(v2 - __bfloat162float(h2));
    }
    // predictor W1 slice for level l: src coalesced, dst scattered
    for (int i = blockIdx.x * 256 + threadIdx.x; i < 256 * HD; i += gridDim.x * 256) {
        int k = i >> 8, j = i & 255;
        float v = Pw1[(size_t)l * HD * 256 + i];
        __nv_bfloat16 h = __float2bfloat16(v);
        size_t dst = (size_t)(l * 256 + j) * HD + k;
        g_pw1t_hi[dst] = h;
        g_pw1t_lo[dst] = __float2bfloat16(v - __bfloat162float(h));
    }
}

// ---------------------------------------------------------------------------
// Predictor GEMM on HMMA: C = X @ Pw1cat (split), epilogue reduces
// relu(c+b1)*w2 into g_logits. grid (8 n-tiles, 512 token-tiles).
// ---------------------------------------------------------------------------
__global__ __launch_bounds__(256) void predictor_mma(
    const float* __restrict__ keys, const float* __restrict__ values,
    const float* __restrict__ Pb1, const float* __restrict__ Pw2)
{
    extern __shared__ char smraw[];
    char* sm = (char*)(((uintptr_t)smraw + 1023u) & ~(uintptr_t)1023u);
    const uint32_t abase = smem_to_u32(sm);
    const int tid = threadIdx.x;
    const int lane = tid & 31, wid = tid >> 5;
    const int m_base = (wid >> 1) * 32, n_base = (wid & 1) * 64;

    const int n0 = blockIdx.x * 128;
    const int lev = blockIdx.x >> 1;
    const int tokbase = blockIdx.y * 128;

    const int r = tid >> 1, seg = tid & 1;
    const int tok = tokbase + r;
    const float* arow = (tok < TOK_HALF)
        ? (keys + (size_t)tok * HD)
        : (values + (size_t)(tok - TOK_HALF) * HD);
    const __nv_bfloat16* bh = g_pw1t_hi + (size_t)(n0 + r) * HD;
    const __nv_bfloat16* bl = g_pw1t_lo + (size_t)(n0 + r) * HD;

    float acc[2][8][4];
#pragma unroll
    for (int mt = 0; mt < 2; mt++)
#pragma unroll
        for (int nt = 0; nt < 8; nt++)
#pragma unroll
            for (int q = 0; q < 4; q++) acc[mt][nt][q] = 0.f;

    for (int kc = 0; kc < HD; kc += 64) {
        const float* ap = arow + kc + seg * 32;
#pragma unroll
        for (int q = 0; q < 4; q++) {
            float4 v0 = *(const float4*)(ap + q * 8);
            float4 v1 = *(const float4*)(ap + q * 8 + 4);
            uint32_t h0, h1, h2, h3, l0, l1, l2, l3;
            h0 = pack_split(v0.x, v0.y, l0);
            h1 = pack_split(v0.z, v0.w, l1);
            h2 = pack_split(v1.x, v1.y, l2);
            h3 = pack_split(v1.z, v1.w, l3);
            uint32_t off = SWZ((uint32_t)(r * 128 + seg * 64 + q * 16));
            STS128(abase + SM_AHI + off, h0, h1, h2, h3);
            STS128(abase + SM_ALO + off, l0, l1, l2, l3);
        }
        const uint4* ph4 = (const uint4*)(bh + kc + seg * 32);
        const uint4* pl4 = (const uint4*)(bl + kc + seg * 32);
#pragma unroll
        for (int q = 0; q < 4; q++) {
            uint32_t off = SWZ((uint32_t)(r * 128 + seg * 64 + q * 16));
            uint4 v = ph4[q];
            STS128(abase + SM_BHI + off, v.x, v.y, v.z, v.w);
            v = pl4[q];
            STS128(abase + SM_BLO + off, v.x, v.y, v.z, v.w);
        }
        __syncthreads();
        mma_chunk(abase + SM_AHI, abase + SM_ALO, abase + SM_BHI, abase + SM_BLO,
                  m_base, n_base, lane, acc);
        __syncthreads();
    }

    // epilogue: logit partial sums in registers
    float b1v[8][2], w2v[8][2];
#pragma unroll
    for (int nt = 0; nt < 8; nt++) {
        int n = n0 + n_base + nt * 8 + ((lane & 3) << 1);
        b1v[nt][0] = Pb1[n];     b1v[nt][1] = Pb1[n + 1];
        w2v[nt][0] = Pw2[n];     w2v[nt][1] = Pw2[n + 1];
    }
#pragma unroll
    for (int mt = 0; mt < 2; mt++) {
        float s0 = 0.f, s1 = 0.f;
#pragma unroll
        for (int nt = 0; nt < 8; nt++) {
            s0 += fmaxf(acc[mt][nt][0] + b1v[nt][0], 0.f) * w2v[nt][0]
                + fmaxf(acc[mt][nt][1] + b1v[nt][1], 0.f) * w2v[nt][1];
            s1 += fmaxf(acc[mt][nt][2] + b1v[nt][0], 0.f) * w2v[nt][0]
                + fmaxf(acc[mt][nt][3] + b1v[nt][1], 0.f) * w2v[nt][1];
        }
        s0 += __shfl_xor_sync(0xffffffffu, s0, 1);
        s0 += __shfl_xor_sync(0xffffffffu, s0, 2);
        s1 += __shfl_xor_sync(0xffffffffu, s1, 1);
        s1 += __shfl_xor_sync(0xffffffffu, s1, 2);
        if ((lane & 3) == 0) {
            int row = m_base + mt * 16 + (lane >> 2);
            atomicAdd(&g_logits[(size_t)(tokbase + row) * NLEV + lev], s0);
            atomicAdd(&g_logits[(size_t)(tokbase + row + 8) * NLEV + lev], s1);
        }
    }
}

// ---------------------------------------------------------------------------
// Gap triage: tokens with top-2 gap under threshold get exact recompute.
// ---------------------------------------------------------------------------
__global__ void detect_kernel(const float* __restrict__ Pb2) {
    int t = blockIdx.x * 256 + threadIdx.x;
    if (t >= TOK_TOTAL) return;
    float v0 = g_logits[t * NLEV + 0] + Pb2[0];
    float v1 = g_logits[t * NLEV + 1] + Pb2[1];
    float v2 = g_logits[t * NLEV + 2] + Pb2[2];
    float v3 = g_logits[t * NLEV + 3] + Pb2[3];
    float m1 = fmaxf(fmaxf(v0, v1), fmaxf(v2, v3));
    // second max: max of values strictly below m1 position; simple approach:
    float s = -1e30f;
    s = (v0 < m1) ? fmaxf(s, v0) : s;
    s = (v1 < m1) ? fmaxf(s, v1) : s;
    s = (v2 < m1) ? fmaxf(s, v2) : s;
    s = (v3 < m1) ? fmaxf(s, v3) : s;
    // ties (exact equal) are themselves ambiguous -> gap 0
    int ties = (v0 == m1) + (v1 == m1) + (v2 == m1) + (v3 == m1);
    float gap = (ties > 1) ? 0.f : (m1 - s);
    if (gap < AMB_THRESH) {
        int p = atomicAdd(&g_amb_count, 1);
        if (p < MAX_AMB) g_amb[p] = t;
    }
}

__global__ void refine_kernel(const float* __restrict__ keys,
                              const float* __restrict__ values,
                              const float* __restrict__ Pw1,
                              const float* __restrict__ Pb1,
                              const float* __restrict__ Pw2) {
    int nAmb = g_amb_count; if (nAmb > MAX_AMB) nAmb = MAX_AMB;
    int i = blockIdx.x >> 2;
    if (i >= nAmb) return;
    int l = blockIdx.x & 3;
    int t = g_amb[i];
    __shared__ float xs[HD];
    __shared__ float red[128];
    const float* x = (t < TOK_HALF) ? keys + (size_t)t * HD
                                    : values + (size_t)(t - TOK_HALF) * HD;
    for (int k = threadIdx.x; k < HD; k += 128) xs[k] = x[k];
    __syncthreads();
    float part = 0.f;
#pragma unroll
    for (int jj = 0; jj < 2; jj++) {
        int j = threadIdx.x + jj * 128;
        float acc = Pb1[l * 256 + j];
        const float* w = Pw1 + (size_t)l * HD * 256 + j;
        for (int k = 0; k < HD; k++) acc = fmaf(xs[k], w[(size_t)k * 256], acc);
        part += fmaxf(acc, 0.f) * Pw2[l * 256 + j];
    }
    red[threadIdx.x] = part;
    __syncthreads();
    for (int s = 64; s > 0; s >>= 1) {
        if (threadIdx.x < s) red[threadIdx.x] += red[threadIdx.x + s];
        __syncthreads();
    }
    if (threadIdx.x == 0) g_logits[(size_t)t * NLEV + l] = red[0];
}

__global__ void argmax_kernel(const float* __restrict__ Pb2) {
    int t = blockIdx.x * 256 + threadIdx.x;
    if (t >= TOK_TOTAL) return;
    float best = g_logits[t * NLEV] + Pb2[0];
    int bl = 0;
#pragma unroll
    for (int l = 1; l < NLEV; l++) {
        float v = g_logits[t * NLEV + l] + Pb2[l];
        if (v > best) { best = v; bl = l; }
    }
    int p = atomicAdd(&g_count[bl], 1);
    g_idx[bl * TOK_TOTAL + p] = t;
}

// ---------------------------------------------------------------------------
// Stage A (HMMA): H = relu(Xg @ w1_l + b1_l) -> bf16 hi/lo
// ---------------------------------------------------------------------------
__global__ __launch_bounds__(256) void stageA_mma(CompParams P) {
    const int lev = blockIdx.z;
    const int d = HD >> lev;
    const int n0 = blockIdx.x * 128;
    if (n0 >= d) return;
    const int cnt = g_count[lev];
    const int m0 = blockIdx.y * 128;
    if (m0 >= cnt) return;

    extern __shared__ char smraw[];
    char* sm = (char*)(((uintptr_t)smraw + 1023u) & ~(uintptr_t)1023u);
    const uint32_t abase = smem_to_u32(sm);
    float* acc_s = (float*)sm;
    const int tid = threadIdx.x;
    const int lane = tid & 31, wid = tid >> 5;
    const int m_base = (wid >> 1) * 32, n_base = (wid & 1) * 64;

    const int r = tid >> 1, seg = tid & 1;
    int rload = m0 + r; if (rload > cnt - 1) rload = cnt - 1;
    const int tgat = g_idx[lev * TOK_TOTAL + rload];
    const float* arow = (tgat < TOK_HALF)
        ? (P.keys + (size_t)tgat * HD)
        : (P.values + (size_t)(tgat - TOK_HALF) * HD);
    const __nv_bfloat16* bh = g_w1t_hi + WOFF(lev) + (size_t)(n0 + r) * HD;
    const __nv_bfloat16* bl = g_w1t_lo + WOFF(lev) + (size_t)(n0 + r) * HD;

    float acc[2][8][4];
#pragma unroll
    for (int mt = 0; mt < 2; mt++)
#pragma unroll
        for (int nt = 0; nt < 8; nt++)
#pragma unroll
            for (int q = 0; q < 4; q++) acc[mt][nt][q] = 0.f;

    for (int kc = 0; kc < HD; kc += 64) {
        const float* ap = arow + kc + seg * 32;
#pragma unroll
        for (int q = 0; q < 4; q++) {
            float4 v0 = *(const float4*)(ap + q * 8);
            float4 v1 = *(const float4*)(ap + q * 8 + 4);
            uint32_t h0, h1, h2, h3, l0, l1, l2, l3;
            h0 = pack_split(v0.x, v0.y, l0);
            h1 = pack_split(v0.z, v0.w, l1);
            h2 = pack_split(v1.x, v1.y, l2);
            h3 = pack_split(v1.z, v1.w, l3);
            uint32_t off = SWZ((uint32_t)(r * 128 + seg * 64 + q * 16));
            STS128(abase + SM_AHI + off, h0, h1, h2, h3);
            STS128(abase + SM_ALO + off, l0, l1, l2, l3);
        }
        const uint4* ph4 = (const uint4*)(bh + kc + seg * 32);
        const uint4* pl4 = (const uint4*)(bl + kc + seg * 32);
#pragma unroll
        for (int q = 0; q < 4; q++) {
            uint32_t off = SWZ((uint32_t)(r * 128 + seg * 64 + q * 16));
            uint4 v = ph4[q];
            STS128(abase + SM_BHI + off, v.x, v.y, v.z, v.w);
            v = pl4[q];
            STS128(abase + SM_BLO + off, v.x, v.y, v.z, v.w);
        }
        __syncthreads();
        mma_chunk(abase + SM_AHI, abase + SM_ALO, abase + SM_BHI, abase + SM_BLO,
                  m_base, n_base, lane, acc);
        __syncthreads();
    }

    stage_acc(acc_s, m_base, n_base, lane, acc);
    __syncthreads();

    // epilogue: relu(+bias), split, store H hi/lo
    {
        const bool live = (m0 + r < cnt);
        int tok = 0;
        if (live) tok = g_idx[lev * TOK_TOTAL + m0 + r];
        const float* src = acc_s + (size_t)r * ACC_LD + seg * 64;
        const float* b1 = P.b1[lev] + n0 + seg * 64;
        if (live) {
            __nv_bfloat16* dh = g_Hhi + (size_t)tok * HD + n0 + seg * 64;
            __nv_bfloat16* dl = g_Hlo + (size_t)tok * HD + n0 + seg * 64;
#pragma unroll
            for (int q = 0; q < 8; q++) {
                float4 v0 = *(const float4*)(src + q * 8);
                float4 v1 = *(const float4*)(src + q * 8 + 4);
                uint32_t hv[4], lv[4];
                hv[0] = pack_split(fmaxf(v0.x + b1[q * 8 + 0], 0.f),
                                   fmaxf(v0.y + b1[q * 8 + 1], 0.f), lv[0]);
                hv[1] = pack_split(fmaxf(v0.z + b1[q * 8 + 2], 0.f),
                                   fmaxf(v0.w + b1[q * 8 + 3], 0.f), lv[1]);
                hv[2] = pack_split(fmaxf(v1.x + b1[q * 8 + 4], 0.f),
                                   fmaxf(v1.y + b1[q * 8 + 5], 0.f), lv[2]);
                hv[3] = pack_split(fmaxf(v1.z + b1[q * 8 + 6], 0.f),
                                   fmaxf(v1.w + b1[q * 8 + 7], 0.f), lv[3]);
                *(uint2*)(dh + q * 8)     = make_uint2(hv[0], hv[1]);
                *(uint2*)(dh + q * 8 + 4) = make_uint2(hv[2], hv[3]);
                *(uint2*)(dl + q * 8)     = make_uint2(lv[0], lv[1]);
                *(uint2*)(dl + q * 8 + 4) = make_uint2(lv[2], lv[3]);
            }
        }
    }
}

// ---------------------------------------------------------------------------
// Stage B (HMMA): out = Hg @ w2_l + b2_l
// ---------------------------------------------------------------------------
__global__ __launch_bounds__(256) void stageB_mma(CompParams P) {
    const int lev = blockIdx.z;
    const int d = HD >> lev;         // K dimension
    const int n0 = blockIdx.x * 128; // N = 1024
    const int cnt = g_count[lev];
    const int m0 = blockIdx.y * 128;
    if (m0 >= cnt) return;

    extern __shared__ char smraw[];
    char* sm = (char*)(((uintptr_t)smraw + 1023u) & ~(uintptr_t)1023u);
    const uint32_t abase = smem_to_u32(sm);
    float* acc_s = (float*)sm;
    const int tid = threadIdx.x;
    const int lane = tid & 31, wid = tid >> 5;
    const int m_base = (wid >> 1) * 32, n_base = (wid & 1) * 64;

    const int r = tid >> 1, seg = tid & 1;
    int rload = m0 + r; if (rload > cnt - 1) rload = cnt - 1;
    const int tgat = g_idx[lev * TOK_TOTAL + rload];
    const __nv_bfloat16* ah = g_Hhi + (size_t)tgat * HD;
    const __nv_bfloat16* al = g_Hlo + (size_t)tgat * HD;
    const __nv_bfloat16* bh = g_w2t_hi + WOFF(lev) + (size_t)(n0 + r) * d;
    const __nv_bfloat16* bl = g_w2t_lo + WOFF(lev) + (size_t)(n0 + r) * d;

    float acc[2][8][4];
#pragma unroll
    for (int mt = 0; mt < 2; mt++)
#pragma unroll
        for (int nt = 0; nt < 8; nt++)
#pragma unroll
            for (int q = 0; q < 4; q++) acc[mt][nt][q] = 0.f;

    for (int kc = 0; kc < d; kc += 64) {
        const uint4* pah = (const uint4*)(ah + kc + seg * 32);
        const uint4* pal = (const uint4*)(al + kc + seg * 32);
        const uint4* pbh = (const uint4*)(bh + kc + seg * 32);
        const uint4* pbl = (const uint4*)(bl + kc + seg * 32);
#pragma unroll
        for (int q = 0; q < 4; q++) {
            uint32_t off = SWZ((uint32_t)(r * 128 + seg * 64 + q * 16));
            uint4 v = pah[q]; STS128(abase + SM_AHI + off, v.x, v.y, v.z, v.w);
            v = pal[q];       STS128(abase + SM_ALO + off, v.x, v.y, v.z, v.w);
            v = pbh[q];       STS128(abase + SM_BHI + off, v.x, v.y, v.z, v.w);
            v = pbl[q];       STS128(abase + SM_BLO + off, v.x, v.y, v.z, v.w);
        }
        __syncthreads();
        mma_chunk(abase + SM_AHI, abase + SM_ALO, abase + SM_BHI, abase + SM_BLO,
                  m_base, n_base, lane, acc);
        __syncthreads();
    }

    stage_acc(acc_s, m_base, n_base, lane, acc);
    __syncthreads();

    {
        const bool live = (m0 + r < cnt);
        int tok = 0;
        if (live) tok = g_idx[lev * TOK_TOTAL + m0 + r];
        const float* src = acc_s + (size_t)r * ACC_LD + seg * 64;
        const float* b2 = P.b2[lev] + n0 + seg * 64;
        if (live) {
            float* dst = P.out + (size_t)tok * HD + n0 + seg * 64;
#pragma unroll
            for (int q = 0; q < 8; q++) {
                float4 v0 = *(const float4*)(src + q * 8);
                float4 v1 = *(const float4*)(src + q * 8 + 4);
                v0.x += b2[q * 8 + 0]; v0.y += b2[q * 8 + 1];
                v0.z += b2[q * 8 + 2]; v0.w += b2[q * 8 + 3];
                v1.x += b2[q * 8 + 4]; v1.y += b2[q * 8 + 5];
                v1.z += b2[q * 8 + 6]; v1.w += b2[q * 8 + 7];
                *(float4*)(dst + q * 8)     = v0;
                *(float4*)(dst + q * 8 + 4) = v1;
            }
        }
    }
}

// ---------------------------------------------------------------------------
extern "C" void kernel_launch(void* const* d_in, const int* in_sizes, int n_in,
                              void* d_out, int out_size) {
    const float* keys   = (const float*)d_in[0];
    const float* values = (const float*)d_in[1];
    const float* Pw1    = (const float*)d_in[2];
    const float* Pb1    = (const float*)d_in[3];
    const float* Pw2    = (const float*)d_in[4];
    const float* Pb2    = (const float*)d_in[5];

    CompParams P;
    P.keys = keys; P.values = values;
    for (int l = 0; l < 4; l++) {
        P.w1[l] = (const float*)d_in[6 + l * 4 + 0];
        P.b1[l] = (const float*)d_in[6 + l * 4 + 1];
        P.w2[l] = (const float*)d_in[6 + l * 4 + 2];
        P.b2[l] = (const float*)d_in[6 + l * 4 + 3];
    }
    P.out = (float*)d_out;

    cudaFuncSetAttribute(predictor_mma, cudaFuncAttributeMaxDynamicSharedMemorySize, SMEM_BYTES);
    cudaFuncSetAttribute(stageA_mma,    cudaFuncAttributeMaxDynamicSharedMemorySize, SMEM_BYTES);
    cudaFuncSetAttribute(stageB_mma,    cudaFuncAttributeMaxDynamicSharedMemorySize, SMEM_BYTES);

    zero_kernel<<<(TOK_TOTAL * NLEV + 255) / 256, 256>>>();

    dim3 wgrid(256, 4);
    prep_kernel<<<wgrid, 256>>>(P, Pw1);

    dim3 pgrid(8, 512);
    predictor_mma<<<pgrid, 256, SMEM_BYTES>>>(keys, values, Pb1, Pw2);

    detect_kernel<<<TOK_TOTAL / 256, 256>>>(Pb2);
    refine_kernel<<<MAX_AMB * 4, 128>>>(keys, values, Pw1, Pb1, Pw2);
    argmax_kernel<<<TOK_TOTAL / 256, 256>>>(Pb2);

    dim3 cgrid(8, 512, 4);
    stageA_mma<<<cgrid, 256, SMEM_BYTES>>>(P);
    stageB_mma<<<cgrid, 256, SMEM_BYTES>>>(P);
}